// round 7
// baseline (speedup 1.0000x reference)
#include <cuda_runtime.h>

#define IN_DIM 128
#define HD     128
#define MAXN   40000
#define MAXE   640000

typedef unsigned long long u64;

// Scratch (allocation-free: __device__ globals)
__device__ float g_Q[MAXN * HD];
__device__ float g_K[MAXN * HD];
__device__ float g_V[MAXN * HD];
__device__ int   g_cnt[MAXN];
__device__ int   g_rowptr[MAXN + 1];
__device__ int   g_cursor[MAXN];
__device__ int   g_eidx[MAXE];   // edge indices grouped by dst
__device__ int   g_srcs[MAXE];   // src[eidx] in ascending-edge order per dst

// Packed dual-FP32 FMA (Blackwell f32x2 pipe). Each half is an independent
// IEEE fp32 fma.rn — bit-identical to two scalar __fmaf_rn.
__device__ __forceinline__ u64 fma2(u64 a, u64 b, u64 c)
{
    u64 d;
    asm("fma.rn.f32x2 %0, %1, %2, %3;" : "=l"(d) : "l"(a), "l"(b), "l"(c));
    return d;
}
__device__ __forceinline__ u64 dup2(float x)
{
    u64 d;
    asm("mov.b64 %0, {%1, %1};" : "=l"(d) : "f"(x));
    return d;
}

// ---------------------------------------------------------------------------
// CSR build: histogram by dst
// ---------------------------------------------------------------------------
__global__ void histogram_kernel(const int* __restrict__ dst, int E)
{
    int e = blockIdx.x * blockDim.x + threadIdx.x;
    if (e < E) atomicAdd(&g_cnt[dst[e]], 1);
}

// Single-block exclusive scan over g_cnt -> g_rowptr / g_cursor
__global__ void scan_kernel(int n)
{
    __shared__ int sm[1024];
    const int t = threadIdx.x;
    const int chunk = (n + 1023) / 1024;
    int b = t * chunk;
    int e = b + chunk; if (e > n) e = n;
    if (b > n) b = n;

    int s = 0;
    for (int i = b; i < e; i++) s += g_cnt[i];
    sm[t] = s;
    __syncthreads();
    for (int off = 1; off < 1024; off <<= 1) {
        int x = (t >= off) ? sm[t - off] : 0;
        __syncthreads();
        sm[t] += x;
        __syncthreads();
    }
    int run = sm[t] - s;
    for (int i = b; i < e; i++) {
        g_rowptr[i] = run;
        g_cursor[i] = run;
        run += g_cnt[i];
    }
    if (t == 1023) g_rowptr[n] = sm[1023];
}

// Scatter EDGE INDICES (intra-row order arbitrary; fixed by rank sort below)
__global__ void scatter_kernel(const int* __restrict__ dst, int E)
{
    int e = blockIdx.x * blockDim.x + threadIdx.x;
    if (e < E) {
        int d = dst[e];
        int pos = atomicAdd(&g_cursor[d], 1);
        g_eidx[pos] = e;
    }
}

// Warp-per-node rank sort. Edge indices are distinct: ascending position of
// x is |{y : y < x}|. d<=32: pure register/shfl path (no smem, no syncwarp).
__global__ __launch_bounds__(256) void sortwarp_kernel(const int* __restrict__ src, int n)
{
    __shared__ int buf[8][128];
    const int warp   = (blockIdx.x * blockDim.x + threadIdx.x) >> 5;
    const int wlocal = (threadIdx.x >> 5);
    const int lane   = threadIdx.x & 31;
    if (warp >= n) return;

    const int beg = g_rowptr[warp];
    const int end = g_rowptr[warp + 1];
    const int d   = end - beg;

    if (d <= 0) return;
    if (d == 1) {
        if (lane == 0) g_srcs[beg] = src[g_eidx[beg]];
        return;
    }
    if (d <= 32) {
        int e = (lane < d) ? g_eidx[beg + lane] : 0x7fffffff;
        int r = 0;
#pragma unroll
        for (int j = 0; j < 32; j++) {
            int x = __shfl_sync(0xffffffffu, e, j);
            r += (x < e);
        }
        if (lane < d) g_srcs[beg + r] = src[e];
        return;
    }
    if (d <= 128) {
        for (int i = lane; i < d; i += 32) buf[wlocal][i] = g_eidx[beg + i];
        __syncwarp();
        for (int i = lane; i < d; i += 32) {
            int e = buf[wlocal][i];
            int r = 0;
            for (int j = 0; j < d; j++) r += (buf[wlocal][j] < e);
            g_srcs[beg + r] = src[e];
        }
    } else if (lane == 0) {  // astronomically unlikely fallback
        for (int i = beg + 1; i < end; i++) {
            int key = g_eidx[i];
            int j = i - 1;
            while (j >= beg && g_eidx[j] > key) { g_eidx[j + 1] = g_eidx[j]; j--; }
            g_eidx[j + 1] = key;
        }
        for (int i = beg; i < end; i++) g_srcs[i] = src[g_eidx[i]];
    }
}

// ---------------------------------------------------------------------------
// QKV GEMM (fp32): C = A[M x 128] * W[128 x 128]  (blockIdx.y: 0=Q, 1=K, 2=V)
// Per output element: one sequential fused-FMA chain over k = 0..127
// ascending (bit-exact vs reference), via packed fma.rn.f32x2.
// Tiling: 128x128 block, BK=16, 256 threads, each thread 4 rows x 16 cols.
// Per k: 1 LDS.128 (a) + 4 LDS.128 (b) + 4 dup-movs + 32 FFMA2.
// ---------------------------------------------------------------------------
__global__ __launch_bounds__(256) void qkv_gemm(
    const float* __restrict__ A,
    const float* __restrict__ WQ,
    const float* __restrict__ WK,
    const float* __restrict__ WV,
    int M)
{
    const float* W = (blockIdx.y == 0) ? WQ : (blockIdx.y == 1) ? WK : WV;
    float* C = (blockIdx.y == 0) ? g_Q : (blockIdx.y == 1) ? g_K : g_V;

    __shared__ float As[16][128];   // [k][m]
    __shared__ float Bs[16][128];   // [k][n]

    const int tid  = threadIdx.x;
    const int row0 = blockIdx.x * 128;

    const int tr = (tid >> 3) * 4;    // 32 row-groups of 4
    const int tc = (tid & 7) * 16;    // 8 col-groups of 16

    const int arow  = tid >> 1;          // 0..127
    const int akcol = (tid & 1) * 8;     // 0 or 8
    const int brow  = tid >> 4;          // 0..15
    const int bcol  = (tid & 15) * 8;    // 0..120

    // acc[i][p] = packed (C[tr+i][tc+2p], C[tr+i][tc+2p+1])
    u64 acc[4][8];
#pragma unroll
    for (int i = 0; i < 4; i++)
#pragma unroll
        for (int p = 0; p < 8; p++) acc[i][p] = 0ULL;

    const bool arow_ok = (row0 + arow < M);

    for (int kc = 0; kc < IN_DIM; kc += 16) {
        float4 av0 = make_float4(0.f, 0.f, 0.f, 0.f);
        float4 av1 = make_float4(0.f, 0.f, 0.f, 0.f);
        if (arow_ok) {
            av0 = *(const float4*)&A[(row0 + arow) * IN_DIM + kc + akcol];
            av1 = *(const float4*)&A[(row0 + arow) * IN_DIM + kc + akcol + 4];
        }
        As[akcol + 0][arow] = av0.x;
        As[akcol + 1][arow] = av0.y;
        As[akcol + 2][arow] = av0.z;
        As[akcol + 3][arow] = av0.w;
        As[akcol + 4][arow] = av1.x;
        As[akcol + 5][arow] = av1.y;
        As[akcol + 6][arow] = av1.z;
        As[akcol + 7][arow] = av1.w;

        *(float4*)&Bs[brow][bcol]     = *(const float4*)&W[(kc + brow) * HD + bcol];
        *(float4*)&Bs[brow][bcol + 4] = *(const float4*)&W[(kc + brow) * HD + bcol + 4];
        __syncthreads();

#pragma unroll
        for (int k = 0; k < 16; k++) {
            float a[4];
            *(float4*)&a[0] = *(const float4*)&As[k][tr];
            ulonglong2 b0 = *(const ulonglong2*)&Bs[k][tc];
            ulonglong2 b1 = *(const ulonglong2*)&Bs[k][tc + 4];
            ulonglong2 b2 = *(const ulonglong2*)&Bs[k][tc + 8];
            ulonglong2 b3 = *(const ulonglong2*)&Bs[k][tc + 12];
#pragma unroll
            for (int i = 0; i < 4; i++) {
                u64 ad = dup2(a[i]);
                acc[i][0] = fma2(ad, b0.x, acc[i][0]);
                acc[i][1] = fma2(ad, b0.y, acc[i][1]);
                acc[i][2] = fma2(ad, b1.x, acc[i][2]);
                acc[i][3] = fma2(ad, b1.y, acc[i][3]);
                acc[i][4] = fma2(ad, b2.x, acc[i][4]);
                acc[i][5] = fma2(ad, b2.y, acc[i][5]);
                acc[i][6] = fma2(ad, b3.x, acc[i][6]);
                acc[i][7] = fma2(ad, b3.y, acc[i][7]);
            }
        }
        __syncthreads();
    }

#pragma unroll
    for (int i = 0; i < 4; i++) {
        int r = row0 + tr + i;
        if (r < M) {
            *(ulonglong2*)&C[r * HD + tc]      = make_ulonglong2(acc[i][0], acc[i][1]);
            *(ulonglong2*)&C[r * HD + tc + 4]  = make_ulonglong2(acc[i][2], acc[i][3]);
            *(ulonglong2*)&C[r * HD + tc + 8]  = make_ulonglong2(acc[i][4], acc[i][5]);
            *(ulonglong2*)&C[r * HD + tc + 12] = make_ulonglong2(acc[i][6], acc[i][7]);
        }
    }
}

// ---------------------------------------------------------------------------
// Edge phase, bit-exact replication in ascending edge order:
//   score = (K[src]*Q[dst]) * 0.25f ; z += score ; wv += V[src]*score
//   out   = wv / (z + 1e-6f)
// One warp per node, 4 channels per lane. Unroll x8: all 16 gathers batched
// before the FP chain (MLP), FP sequence unchanged.
// ---------------------------------------------------------------------------
__device__ __forceinline__ void edge_step(float4 k, float4 v, const float4& q,
                                          float4& z, float4& w)
{
    float sc0 = __fmul_rn(__fmul_rn(k.x, q.x), 0.25f);
    float sc1 = __fmul_rn(__fmul_rn(k.y, q.y), 0.25f);
    float sc2 = __fmul_rn(__fmul_rn(k.z, q.z), 0.25f);
    float sc3 = __fmul_rn(__fmul_rn(k.w, q.w), 0.25f);
    z.x = __fadd_rn(z.x, sc0);
    z.y = __fadd_rn(z.y, sc1);
    z.z = __fadd_rn(z.z, sc2);
    z.w = __fadd_rn(z.w, sc3);
    w.x = __fadd_rn(w.x, __fmul_rn(v.x, sc0));
    w.y = __fadd_rn(w.y, __fmul_rn(v.y, sc1));
    w.z = __fadd_rn(w.z, __fmul_rn(v.z, sc2));
    w.w = __fadd_rn(w.w, __fmul_rn(v.w, sc3));
}

__global__ __launch_bounds__(256) void aggregate_kernel(float* __restrict__ out, int n)
{
    int node = (blockIdx.x * blockDim.x + threadIdx.x) >> 5;
    if (node >= n) return;
    const int lane = threadIdx.x & 31;

    const int beg = g_rowptr[node];
    const int end = g_rowptr[node + 1];

    const float4* __restrict__ K4 = (const float4*)g_K;
    const float4* __restrict__ V4 = (const float4*)g_V;

    float4 q = ((const float4*)g_Q)[node * 32 + lane];

    float4 z = make_float4(0.f, 0.f, 0.f, 0.f);
    float4 w = make_float4(0.f, 0.f, 0.f, 0.f);

    int j = beg;
    for (; j + 8 <= end; j += 8) {
        int s[8];
#pragma unroll
        for (int u = 0; u < 8; u++) s[u] = g_srcs[j + u];
        float4 kk[8], vv[8];
#pragma unroll
        for (int u = 0; u < 8; u++) {
            kk[u] = K4[s[u] * 32 + lane];
            vv[u] = V4[s[u] * 32 + lane];
        }
#pragma unroll
        for (int u = 0; u < 8; u++) edge_step(kk[u], vv[u], q, z, w);
    }
    for (; j + 4 <= end; j += 4) {
        int s0 = g_srcs[j + 0];
        int s1 = g_srcs[j + 1];
        int s2 = g_srcs[j + 2];
        int s3 = g_srcs[j + 3];
        float4 k0 = K4[s0 * 32 + lane], v0 = V4[s0 * 32 + lane];
        float4 k1 = K4[s1 * 32 + lane], v1 = V4[s1 * 32 + lane];
        float4 k2 = K4[s2 * 32 + lane], v2 = V4[s2 * 32 + lane];
        float4 k3 = K4[s3 * 32 + lane], v3 = V4[s3 * 32 + lane];
        edge_step(k0, v0, q, z, w);
        edge_step(k1, v1, q, z, w);
        edge_step(k2, v2, q, z, w);
        edge_step(k3, v3, q, z, w);
    }
    for (; j < end; j++) {
        int s = g_srcs[j];
        edge_step(K4[s * 32 + lane], V4[s * 32 + lane], q, z, w);
    }

    float4 r;
    r.x = __fdiv_rn(w.x, __fadd_rn(z.x, 1e-6f));
    r.y = __fdiv_rn(w.y, __fadd_rn(z.y, 1e-6f));
    r.z = __fdiv_rn(w.z, __fadd_rn(z.z, 1e-6f));
    r.w = __fdiv_rn(w.w, __fadd_rn(z.w, 1e-6f));

    ((float4*)out)[node * 32 + lane] = r;
}

// ---------------------------------------------------------------------------
extern "C" void kernel_launch(void* const* d_in, const int* in_sizes, int n_in,
                              void* d_out, int out_size)
{
    const float* h   = (const float*)d_in[0];
    const int*   src = (const int*)  d_in[1];
    const int*   dst = (const int*)  d_in[2];
    const float* WQ  = (const float*)d_in[3];
    const float* WK  = (const float*)d_in[4];
    const float* WV  = (const float*)d_in[5];
    float* out = (float*)d_out;

    const int N = in_sizes[0] / IN_DIM;
    const int E = in_sizes[1];

    void* cntPtr = nullptr;
    cudaGetSymbolAddress(&cntPtr, g_cnt);
    cudaMemsetAsync(cntPtr, 0, (size_t)N * sizeof(int));

    histogram_kernel<<<(E + 511) / 512, 512>>>(dst, E);
    scan_kernel<<<1, 1024>>>(N);
    scatter_kernel<<<(E + 511) / 512, 512>>>(dst, E);
    sortwarp_kernel<<<(N * 32 + 255) / 256, 256>>>(src, N);

    dim3 ggrid((N + 127) / 128, 3);
    qkv_gemm<<<ggrid, 256>>>(h, WQ, WK, WV, N);

    aggregate_kernel<<<(N * 32 + 255) / 256, 256>>>(out, N);
}

// round 8
// speedup vs baseline: 1.8206x; 1.8206x over previous
#include <cuda_runtime.h>

#define IN_DIM 128
#define HD     128
#define MAXN   40000
#define MAXE   640000

typedef unsigned long long u64;

// Scratch (allocation-free: __device__ globals)
__device__ float g_Q[MAXN * HD];
__device__ float g_K[MAXN * HD];
__device__ float g_V[MAXN * HD];
__device__ int   g_cnt[MAXN];
__device__ int   g_rowptr[MAXN + 1];
__device__ int   g_cursor[MAXN];
__device__ int   g_eidx[MAXE];   // edge indices grouped by dst
__device__ int   g_srcs[MAXE];   // src[eidx] in ascending-edge order per dst

// Packed dual-FP32 FMA (Blackwell f32x2 pipe). Each half is an independent
// IEEE fp32 fma.rn — bit-identical to two scalar __fmaf_rn.
__device__ __forceinline__ u64 fma2(u64 a, u64 b, u64 c)
{
    u64 d;
    asm("fma.rn.f32x2 %0, %1, %2, %3;" : "=l"(d) : "l"(a), "l"(b), "l"(c));
    return d;
}
__device__ __forceinline__ u64 dup2(float x)
{
    u64 d;
    asm("mov.b64 %0, {%1, %1};" : "=l"(d) : "f"(x));
    return d;
}

// ---------------------------------------------------------------------------
// CSR build: histogram by dst
// ---------------------------------------------------------------------------
__global__ void histogram_kernel(const int* __restrict__ dst, int E)
{
    int e = blockIdx.x * blockDim.x + threadIdx.x;
    if (e < E) atomicAdd(&g_cnt[dst[e]], 1);
}

// Single-block exclusive scan over g_cnt -> g_rowptr / g_cursor
__global__ void scan_kernel(int n)
{
    __shared__ int sm[1024];
    const int t = threadIdx.x;
    const int chunk = (n + 1023) / 1024;
    int b = t * chunk;
    int e = b + chunk; if (e > n) e = n;
    if (b > n) b = n;

    int s = 0;
    for (int i = b; i < e; i++) s += g_cnt[i];
    sm[t] = s;
    __syncthreads();
    for (int off = 1; off < 1024; off <<= 1) {
        int x = (t >= off) ? sm[t - off] : 0;
        __syncthreads();
        sm[t] += x;
        __syncthreads();
    }
    int run = sm[t] - s;
    for (int i = b; i < e; i++) {
        g_rowptr[i] = run;
        g_cursor[i] = run;
        run += g_cnt[i];
    }
    if (t == 1023) g_rowptr[n] = sm[1023];
}

// Scatter EDGE INDICES (intra-row order arbitrary; fixed by rank sort below)
__global__ void scatter_kernel(const int* __restrict__ dst, int E)
{
    int e = blockIdx.x * blockDim.x + threadIdx.x;
    if (e < E) {
        int d = dst[e];
        int pos = atomicAdd(&g_cursor[d], 1);
        g_eidx[pos] = e;
    }
}

// Warp-per-node rank sort. Edge indices are distinct: ascending position of
// x is |{y : y < x}|. d<=32: pure register/shfl path (no smem, no syncwarp).
__global__ __launch_bounds__(256) void sortwarp_kernel(const int* __restrict__ src, int n)
{
    __shared__ int buf[8][128];
    const int warp   = (blockIdx.x * blockDim.x + threadIdx.x) >> 5;
    const int wlocal = (threadIdx.x >> 5);
    const int lane   = threadIdx.x & 31;
    if (warp >= n) return;

    const int beg = g_rowptr[warp];
    const int end = g_rowptr[warp + 1];
    const int d   = end - beg;

    if (d <= 0) return;
    if (d == 1) {
        if (lane == 0) g_srcs[beg] = src[g_eidx[beg]];
        return;
    }
    if (d <= 32) {
        int e = (lane < d) ? g_eidx[beg + lane] : 0x7fffffff;
        int r = 0;
#pragma unroll
        for (int j = 0; j < 32; j++) {
            int x = __shfl_sync(0xffffffffu, e, j);
            r += (x < e);
        }
        if (lane < d) g_srcs[beg + r] = src[e];
        return;
    }
    if (d <= 128) {
        for (int i = lane; i < d; i += 32) buf[wlocal][i] = g_eidx[beg + i];
        __syncwarp();
        for (int i = lane; i < d; i += 32) {
            int e = buf[wlocal][i];
            int r = 0;
            for (int j = 0; j < d; j++) r += (buf[wlocal][j] < e);
            g_srcs[beg + r] = src[e];
        }
    } else if (lane == 0) {  // astronomically unlikely fallback
        for (int i = beg + 1; i < end; i++) {
            int key = g_eidx[i];
            int j = i - 1;
            while (j >= beg && g_eidx[j] > key) { g_eidx[j + 1] = g_eidx[j]; j--; }
            g_eidx[j + 1] = key;
        }
        for (int i = beg; i < end; i++) g_srcs[i] = src[g_eidx[i]];
    }
}

// ---------------------------------------------------------------------------
// QKV GEMM (fp32) — R6-measured-good version.
// C = A[M x 128] * W[128 x 128]  (blockIdx.y: 0=Q, 1=K, 2=V)
// Per output element: one sequential fused-FMA chain over k = 0..127
// ascending (bit-exact vs reference), packed fma.rn.f32x2 over column pairs.
// 128x128 block tile, BK=8, 256 threads, 8 rows x 8 cols per thread.
// ---------------------------------------------------------------------------
__global__ __launch_bounds__(256) void qkv_gemm(
    const float* __restrict__ A,
    const float* __restrict__ WQ,
    const float* __restrict__ WK,
    const float* __restrict__ WV,
    int M)
{
    const float* W = (blockIdx.y == 0) ? WQ : (blockIdx.y == 1) ? WK : WV;
    float* C = (blockIdx.y == 0) ? g_Q : (blockIdx.y == 1) ? g_K : g_V;

    __shared__ float As[8][128];
    __shared__ float Bs[8][128];

    const int tid  = threadIdx.x;
    const int row0 = blockIdx.x * 128;

    const int tr = (tid >> 4) * 8;
    const int tc = (tid & 15) * 8;

    const int arow  = tid >> 1;
    const int akcol = (tid & 1) * 4;
    const int brow = tid >> 5;
    const int bcol = (tid & 31) * 4;

    // acc2[i][p] = packed (C[tr+i][tc+2p], C[tr+i][tc+2p+1])
    u64 acc2[8][4];
#pragma unroll
    for (int i = 0; i < 8; i++)
#pragma unroll
        for (int p = 0; p < 4; p++) acc2[i][p] = 0ULL;

    for (int kc = 0; kc < IN_DIM; kc += 8) {
        float4 av = make_float4(0.f, 0.f, 0.f, 0.f);
        if (row0 + arow < M)
            av = *(const float4*)&A[(row0 + arow) * IN_DIM + kc + akcol];
        As[akcol + 0][arow] = av.x;
        As[akcol + 1][arow] = av.y;
        As[akcol + 2][arow] = av.z;
        As[akcol + 3][arow] = av.w;

        float4 bv = *(const float4*)&W[(kc + brow) * HD + bcol];
        *(float4*)&Bs[brow][bcol] = bv;
        __syncthreads();

#pragma unroll
        for (int k = 0; k < 8; k++) {
            float a[8];
            *(float4*)&a[0] = *(const float4*)&As[k][tr];
            *(float4*)&a[4] = *(const float4*)&As[k][tr + 4];
            ulonglong2 bl = *(const ulonglong2*)&Bs[k][tc];
            ulonglong2 bh = *(const ulonglong2*)&Bs[k][tc + 4];
#pragma unroll
            for (int i = 0; i < 8; i++) {
                u64 ad = dup2(a[i]);
                acc2[i][0] = fma2(ad, bl.x, acc2[i][0]);
                acc2[i][1] = fma2(ad, bl.y, acc2[i][1]);
                acc2[i][2] = fma2(ad, bh.x, acc2[i][2]);
                acc2[i][3] = fma2(ad, bh.y, acc2[i][3]);
            }
        }
        __syncthreads();
    }

#pragma unroll
    for (int i = 0; i < 8; i++) {
        int r = row0 + tr + i;
        if (r < M) {
            *(ulonglong2*)&C[r * HD + tc]     = make_ulonglong2(acc2[i][0], acc2[i][1]);
            *(ulonglong2*)&C[r * HD + tc + 4] = make_ulonglong2(acc2[i][2], acc2[i][3]);
        }
    }
}

// ---------------------------------------------------------------------------
// Edge phase (R6-measured-good, unroll x4 — x8 spilled in R7):
//   score = (K[src]*Q[dst]) * 0.25f ; z += score ; wv += V[src]*score
//   out   = wv / (z + 1e-6f)        all in ascending edge order, bit-exact.
// ---------------------------------------------------------------------------
__device__ __forceinline__ void edge_step(float4 k, float4 v, const float4& q,
                                          float4& z, float4& w)
{
    float sc0 = __fmul_rn(__fmul_rn(k.x, q.x), 0.25f);
    float sc1 = __fmul_rn(__fmul_rn(k.y, q.y), 0.25f);
    float sc2 = __fmul_rn(__fmul_rn(k.z, q.z), 0.25f);
    float sc3 = __fmul_rn(__fmul_rn(k.w, q.w), 0.25f);
    z.x = __fadd_rn(z.x, sc0);
    z.y = __fadd_rn(z.y, sc1);
    z.z = __fadd_rn(z.z, sc2);
    z.w = __fadd_rn(z.w, sc3);
    w.x = __fadd_rn(w.x, __fmul_rn(v.x, sc0));
    w.y = __fadd_rn(w.y, __fmul_rn(v.y, sc1));
    w.z = __fadd_rn(w.z, __fmul_rn(v.z, sc2));
    w.w = __fadd_rn(w.w, __fmul_rn(v.w, sc3));
}

__global__ __launch_bounds__(256) void aggregate_kernel(float* __restrict__ out, int n)
{
    int node = (blockIdx.x * blockDim.x + threadIdx.x) >> 5;
    if (node >= n) return;
    const int lane = threadIdx.x & 31;

    const int beg = g_rowptr[node];
    const int end = g_rowptr[node + 1];

    const float4* __restrict__ K4 = (const float4*)g_K;
    const float4* __restrict__ V4 = (const float4*)g_V;

    float4 q = ((const float4*)g_Q)[node * 32 + lane];

    float4 z = make_float4(0.f, 0.f, 0.f, 0.f);
    float4 w = make_float4(0.f, 0.f, 0.f, 0.f);

    int j = beg;
    for (; j + 4 <= end; j += 4) {
        int s0 = g_srcs[j + 0];
        int s1 = g_srcs[j + 1];
        int s2 = g_srcs[j + 2];
        int s3 = g_srcs[j + 3];
        float4 k0 = K4[s0 * 32 + lane], v0 = V4[s0 * 32 + lane];
        float4 k1 = K4[s1 * 32 + lane], v1 = V4[s1 * 32 + lane];
        float4 k2 = K4[s2 * 32 + lane], v2 = V4[s2 * 32 + lane];
        float4 k3 = K4[s3 * 32 + lane], v3 = V4[s3 * 32 + lane];
        edge_step(k0, v0, q, z, w);
        edge_step(k1, v1, q, z, w);
        edge_step(k2, v2, q, z, w);
        edge_step(k3, v3, q, z, w);
    }
    for (; j < end; j++) {
        int s = g_srcs[j];
        edge_step(K4[s * 32 + lane], V4[s * 32 + lane], q, z, w);
    }

    float4 r;
    r.x = __fdiv_rn(w.x, __fadd_rn(z.x, 1e-6f));
    r.y = __fdiv_rn(w.y, __fadd_rn(z.y, 1e-6f));
    r.z = __fdiv_rn(w.z, __fadd_rn(z.z, 1e-6f));
    r.w = __fdiv_rn(w.w, __fadd_rn(z.w, 1e-6f));

    ((float4*)out)[node * 32 + lane] = r;
}

// ---------------------------------------------------------------------------
// Launch: fork the (independent) QKV GEMM onto a second capture stream so the
// CSR-build chain overlaps it in the captured graph; join before aggregate.
// Streams/events are host objects (no device memory) created fresh per call.
// ---------------------------------------------------------------------------
extern "C" void kernel_launch(void* const* d_in, const int* in_sizes, int n_in,
                              void* d_out, int out_size)
{
    const float* h   = (const float*)d_in[0];
    const int*   src = (const int*)  d_in[1];
    const int*   dst = (const int*)  d_in[2];
    const float* WQ  = (const float*)d_in[3];
    const float* WK  = (const float*)d_in[4];
    const float* WV  = (const float*)d_in[5];
    float* out = (float*)d_out;

    const int N = in_sizes[0] / IN_DIM;
    const int E = in_sizes[1];

    // Try to set up a parallel branch for the GEMM
    cudaStream_t s2 = nullptr;
    cudaEvent_t evFork = nullptr, evJoin = nullptr;
    bool forked =
        (cudaStreamCreateWithFlags(&s2, cudaStreamNonBlocking) == cudaSuccess) &&
        (cudaEventCreateWithFlags(&evFork, cudaEventDisableTiming) == cudaSuccess) &&
        (cudaEventCreateWithFlags(&evJoin, cudaEventDisableTiming) == cudaSuccess);

    dim3 ggrid((N + 127) / 128, 3);

    if (forked) {
        // Fork: GEMM branch on s2
        forked = (cudaEventRecord(evFork, 0) == cudaSuccess) &&
                 (cudaStreamWaitEvent(s2, evFork, 0) == cudaSuccess);
    }
    if (forked) {
        qkv_gemm<<<ggrid, 256, 0, s2>>>(h, WQ, WK, WV, N);
        forked = (cudaEventRecord(evJoin, s2) == cudaSuccess);
    }

    // CSR-build chain on the main (captured) stream
    void* cntPtr = nullptr;
    cudaGetSymbolAddress(&cntPtr, g_cnt);
    cudaMemsetAsync(cntPtr, 0, (size_t)N * sizeof(int));

    histogram_kernel<<<(E + 511) / 512, 512>>>(dst, E);
    scan_kernel<<<1, 1024>>>(N);
    scatter_kernel<<<(E + 511) / 512, 512>>>(dst, E);
    sortwarp_kernel<<<(N * 32 + 255) / 256, 256>>>(src, N);

    if (forked) {
        // Join GEMM branch back into the main stream
        cudaStreamWaitEvent(0, evJoin, 0);
    } else {
        // Fallback: serialized GEMM on the main stream
        qkv_gemm<<<ggrid, 256>>>(h, WQ, WK, WV, N);
    }

    aggregate_kernel<<<(N * 32 + 255) / 256, 256>>>(out, N);
}